// round 17
// baseline (speedup 1.0000x reference)
#include <cuda_runtime.h>
#include <cuda_fp16.h>
#include <cstdint>
#include <cstddef>

// Problem constants
#define N_SRC0   286000
#define N_DST0   11000
#define N_E0     275000
#define N_DST1   1000
#define N_E1     10000
#define F_IN     602
#define HID      256
#define NCLS     41
#define KPAD     640          // 10 chunks of 64 (fp16 path)
#define F2       (F_IN / 2)   // 301
#define P2       (KPAD / 2)   // 320
#define KCH      10           // K64-chunks per phase

// k-permutation within each 16-k group: [k0k1 k8k9 | k2k3 k10k11 | k4k5 k12k13 | k6k7 k14k15]
__device__ __forceinline__ int hperm(int k) {
    int kk = k & 15;
    int p = kk >> 1, b = kk & 1;
    int o = (p < 4) ? (p * 4 + b) : ((p - 4) * 4 + 2 + b);
    return (k & ~15) | o;
}

// ---------------- scratch (device globals; zero-initialized at load) --------
__device__ int g_cnt0[N_DST0];          // zeroed by k_scan after each use
__device__ int g_off0[N_DST0 + 1];
__device__ int g_src0[N_E0];
__device__ int g_rank0[N_E0];
__device__ int g_cnt1[N_DST1];
__device__ int g_off1[N_DST1 + 1];
__device__ int g_src1[N_E1];
__device__ int g_rank1[N_E1];

// fp16 operand buffers, k-permuted layout (padded to KPAD)
__device__ __align__(16) __half g_xt  [(size_t)N_DST0 * KPAD];
__device__ __align__(16) __half g_hagg[(size_t)N_DST0 * KPAD];
__device__ __align__(16) __half g_wts [256 * KPAD];              // Wself0^T  [n][k]
__device__ __align__(16) __half g_wtn [256 * KPAD];              // Wneigh0^T [n][k]

__device__ float g_h[(size_t)N_DST0 * HID];

// ---------------- CSR build --------------------------------------------------
__global__ void k_count(const int* __restrict__ e0_dst, const int* __restrict__ e1_dst) {
    int i = blockIdx.x * blockDim.x + threadIdx.x;
    if (i < N_E0) g_rank0[i] = atomicAdd(&g_cnt0[e0_dst[i]], 1);
    if (i < N_E1) g_rank1[i] = atomicAdd(&g_cnt1[e1_dst[i]], 1);
}

// scan: exclusive prefix of cnt -> off, re-zeroing cnt for the next replay
__device__ void scan_excl(int* cnt, int* off, int n) {
    __shared__ int wsum[32];
    __shared__ int carry;
    const int t = threadIdx.x, lane = t & 31, w = t >> 5;
    if (t == 0) carry = 0;
    __syncthreads();
    for (int base = 0; base < n; base += 1024) {
        int i = base + t;
        int v = (i < n) ? cnt[i] : 0;
        int s = v;
        #pragma unroll
        for (int d = 1; d < 32; d <<= 1) { int u = __shfl_up_sync(~0u, s, d); if (lane >= d) s += u; }
        if (lane == 31) wsum[w] = s;
        __syncthreads();
        if (w == 0) {
            int ws = wsum[lane];
            #pragma unroll
            for (int d = 1; d < 32; d <<= 1) { int u = __shfl_up_sync(~0u, ws, d); if (lane >= d) ws += u; }
            wsum[lane] = ws;
        }
        __syncthreads();
        int woff = (w > 0) ? wsum[w - 1] : 0;
        if (i < n) { off[i] = carry + woff + s - v; cnt[i] = 0; }
        __syncthreads();
        if (t == 0) carry += wsum[31];
        __syncthreads();
    }
    if (threadIdx.x == 0) off[n] = carry;
}

__global__ void k_scan() {
    if (blockIdx.x == 0) scan_excl(g_cnt0, g_off0, N_DST0);
    else                 scan_excl(g_cnt1, g_off1, N_DST1);
}

// scatter: atomic-free (rank precomputed in k_count)
__global__ void k_scatter(const int* __restrict__ e0_src, const int* __restrict__ e0_dst,
                          const int* __restrict__ e1_src, const int* __restrict__ e1_dst) {
    int i = blockIdx.x * blockDim.x + threadIdx.x;
    if (i < N_E0)
        g_src0[g_off0[e0_dst[i]] + g_rank0[i]] = e0_src[i];
    if (i < N_E1)
        g_src1[g_off1[e1_dst[i]] + g_rank1[i]] = e1_src[i];
}

// ---------------- mega kernel: agg0 (first) + prepx + prepw filler ----------
#define PX2_BLKS ((N_DST0 * P2 + 255) / 256)     // 13750
#define PW2_BLKS ((2 * 256 * KPAD + 255) / 256)  // 1280
#define MEGA_BLKS (N_DST0 + PX2_BLKS + PW2_BLKS)

__device__ __forceinline__ void agg0_body(int dst, const float* __restrict__ x) {
    const int beg = g_off0[dst];
    const int end = g_off0[dst + 1];
    const int t   = threadIdx.x;

    float2 acc0 = make_float2(0.f, 0.f);
    float2 acc1 = make_float2(0.f, 0.f);
    float2 acc2 = make_float2(0.f, 0.f);
    const bool has3 = (t + 256) < F2;

    int e = beg;
    if (e + 6 <= end) {
        // software-pipelined 6-edge unroll: 18 independent LDG.64 in flight
        // per thread; next iteration's indices prefetched before consumption.
        int s0 = g_src0[e + 0], s1 = g_src0[e + 1], s2 = g_src0[e + 2];
        int s3 = g_src0[e + 3], s4 = g_src0[e + 4], s5 = g_src0[e + 5];
        for (; e + 6 <= end; ) {
            const float2* r0 = reinterpret_cast<const float2*>(x + (size_t)s0 * F_IN);
            const float2* r1 = reinterpret_cast<const float2*>(x + (size_t)s1 * F_IN);
            const float2* r2 = reinterpret_cast<const float2*>(x + (size_t)s2 * F_IN);
            const float2* r3 = reinterpret_cast<const float2*>(x + (size_t)s3 * F_IN);
            const float2* r4 = reinterpret_cast<const float2*>(x + (size_t)s4 * F_IN);
            const float2* r5 = reinterpret_cast<const float2*>(x + (size_t)s5 * F_IN);
            float2 a0 = __ldg(r0 + t),       b0 = __ldg(r1 + t),       c0 = __ldg(r2 + t);
            float2 d0 = __ldg(r3 + t),       f0 = __ldg(r4 + t),       h0 = __ldg(r5 + t);
            float2 a1 = __ldg(r0 + t + 128), b1 = __ldg(r1 + t + 128), c1 = __ldg(r2 + t + 128);
            float2 d1 = __ldg(r3 + t + 128), f1 = __ldg(r4 + t + 128), h1 = __ldg(r5 + t + 128);
            float2 a2, b2, c2, d2, f2, h2;
            if (has3) {
                a2 = __ldg(r0 + t + 256); b2 = __ldg(r1 + t + 256); c2 = __ldg(r2 + t + 256);
                d2 = __ldg(r3 + t + 256); f2 = __ldg(r4 + t + 256); h2 = __ldg(r5 + t + 256);
            }
            e += 6;
            if (e + 6 <= end) {   // prefetch next indices before consuming loads
                s0 = g_src0[e + 0]; s1 = g_src0[e + 1]; s2 = g_src0[e + 2];
                s3 = g_src0[e + 3]; s4 = g_src0[e + 4]; s5 = g_src0[e + 5];
            }
            acc0.x += (a0.x + b0.x) + (c0.x + d0.x) + (f0.x + h0.x);
            acc0.y += (a0.y + b0.y) + (c0.y + d0.y) + (f0.y + h0.y);
            acc1.x += (a1.x + b1.x) + (c1.x + d1.x) + (f1.x + h1.x);
            acc1.y += (a1.y + b1.y) + (c1.y + d1.y) + (f1.y + h1.y);
            if (has3) {
                acc2.x += (a2.x + b2.x) + (c2.x + d2.x) + (f2.x + h2.x);
                acc2.y += (a2.y + b2.y) + (c2.y + d2.y) + (f2.y + h2.y);
            }
        }
    }
    for (; e < end; ++e) {
        const float2* row = reinterpret_cast<const float2*>(x + (size_t)g_src0[e] * F_IN);
        float2 v0 = __ldg(row + t);
        float2 v1 = __ldg(row + t + 128);
        acc0.x += v0.x; acc0.y += v0.y;
        acc1.x += v1.x; acc1.y += v1.y;
        if (has3) {
            float2 v2 = __ldg(row + t + 256);
            acc2.x += v2.x; acc2.y += v2.y;
        }
    }

    const float inv = (end > beg) ? 1.0f / (float)(end - beg) : 0.0f;
    __half* o = g_hagg + (size_t)dst * KPAD;
    float2 accs[3] = {acc0, acc1, acc2};
    #pragma unroll
    for (int j = 0; j < 3; ++j) {
        int p = t + j * 128;
        if (p >= P2) break;
        float vx = (p < F2) ? accs[j].x * inv : 0.f;
        float vy = (p < F2) ? accs[j].y * inv : 0.f;
        *reinterpret_cast<half2*>(o + hperm(2 * p)) = __floats2half2_rn(vx, vy);
    }
}

// launch_bounds(128, 6): 85-reg budget so the 18-load flight group stays fully
// in registers; 24 warps/SM still queue more total loads than R15's 32x12.
__global__ __launch_bounds__(128, 6)
void k_agg0_prep(const float* __restrict__ x,
                 const float* __restrict__ Ws, const float* __restrict__ Wn) {
    const int bx = blockIdx.x;
    if (bx < N_DST0) {
        agg0_body(bx, x);
    } else if (bx < N_DST0 + PX2_BLKS) {
        int base = (bx - N_DST0) * 256;
        #pragma unroll
        for (int u = 0; u < 2; ++u) {
            int idx = base + threadIdx.x + u * 128;
            if (idx >= N_DST0 * P2) break;
            int row = idx / P2;
            int p   = idx % P2;
            float2 v = make_float2(0.f, 0.f);
            if (p < F2) v = reinterpret_cast<const float2*>(x)[(size_t)row * F2 + p];
            __half* dst = g_xt + (size_t)row * KPAD;
            *reinterpret_cast<half2*>(dst + hperm(2 * p)) = __floats2half2_rn(v.x, v.y);
        }
    } else {
        int base = (bx - N_DST0 - PX2_BLKS) * 256;
        #pragma unroll
        for (int u = 0; u < 2; ++u) {
            int idx = base + threadIdx.x + u * 128;
            if (idx >= 2 * 256 * KPAD) break;
            int m = idx / (256 * KPAD);
            int r = idx % (256 * KPAD);
            int n = r / KPAD;
            int k = r % KPAD;
            const float* W = m ? Wn : Ws;
            float v = (k < F_IN) ? W[(size_t)k * HID + n] : 0.0f;
            __half h = __float2half_rn(v);
            int d = n * KPAD + hperm(k);
            if (m) g_wtn[d] = h;
            else   g_wts[d] = h;
        }
    }
}

// ---------------- tensor-core GEMM via mma.sync (FP16, sm_80+ PTX) ----------
#define BK        64
#define ROWPH     80                       // padded row length (halves)
#define ROWB      (ROWPH * 2)              // 160 B
#define A_T       (128 * ROWB)             // 20480 B
#define B_T       (64 * ROWB)              // 10240 B
#define BUF_SZ    (A_T + B_T)              // 30720 B
#define GEMM_SMEM (2 * BUF_SZ)             // 61440 B
#define NCH       (2 * KCH)                // 20

#define CP16(dst, src, pred) \
    asm volatile("cp.async.cg.shared.global [%0], [%1], 16, %2;" \
                 :: "r"(dst), "l"(src), "r"(pred))
#define CP_COMMIT() asm volatile("cp.async.commit_group;" ::: "memory")
#define CP_WAIT(n)  asm volatile("cp.async.wait_group %0;" :: "n"(n) : "memory")

__device__ __forceinline__ uint32_t smem_u32(const void* p) {
    uint32_t a;
    asm("{ .reg .u64 t; cvta.to.shared.u64 t, %1; cvt.u32.u64 %0, t; }" : "=r"(a) : "l"(p));
    return a;
}

__device__ __forceinline__ void mma_f16(float* d,
                                        const uint32_t* a, const uint32_t* b) {
    asm volatile(
        "mma.sync.aligned.m16n8k16.row.col.f32.f16.f16.f32 "
        "{%0,%1,%2,%3}, {%4,%5,%6,%7}, {%8,%9}, {%0,%1,%2,%3};"
        : "+f"(d[0]), "+f"(d[1]), "+f"(d[2]), "+f"(d[3])
        : "r"(a[0]), "r"(a[1]), "r"(a[2]), "r"(a[3]), "r"(b[0]), "r"(b[1]));
}

__global__ __launch_bounds__(256, 3)
void k_gemm_mma(const float* __restrict__ bias) {
    extern __shared__ char smem[];
    const uint32_t sb = smem_u32(smem);
    const int tid  = threadIdx.x;
    const int lane = tid & 31;
    const int wid  = tid >> 5;
    const int warpM = wid & 3;
    const int warpN = wid >> 2;
    const int g  = lane >> 2;
    const int tg = lane & 3;
    const int rowBase = blockIdx.x * 128;
    const int colBase = blockIdx.y * 64;

    auto issue = [&](int c) {
        const int ph = (c >= KCH);
        const int kb = (c - ph * KCH) * BK;            // half-index
        const __half* A = ph ? g_hagg : g_xt;
        const __half* B = ph ? g_wtn : g_wts;
        const uint32_t bufb = sb + (uint32_t)(c & 1) * BUF_SZ;

        #pragma unroll
        for (int u = 0; u < 4; ++u) {
            int idx = tid + u * 256;          // 0..1023
            int row = idx >> 3, v = idx & 7;
            int grow = rowBase + row;
            int pr = (grow < N_DST0) ? 16 : 0;
            size_t gb = ((size_t)grow * KPAD + kb) * 2 + v * 16;
            if (grow >= N_DST0) gb = 0;
            uint32_t so = bufb + (uint32_t)(row * ROWB + v * 16);
            CP16(so, (const char*)A + gb, pr);
        }
        #pragma unroll
        for (int u = 0; u < 2; ++u) {
            int idx = tid + u * 256;          // 0..511
            int row = idx >> 3, v = idx & 7;
            size_t gb = ((size_t)(colBase + row) * KPAD + kb) * 2 + v * 16;
            uint32_t so = bufb + (uint32_t)(A_T + row * ROWB + v * 16);
            CP16(so, (const char*)B + gb, 16);
        }
    };

    float acc[2][4][4] = {};

    issue(0);
    CP_COMMIT();

    for (int c = 0; c < NCH; ++c) {
        if (c + 1 < NCH) { issue(c + 1); CP_COMMIT(); CP_WAIT(1); }
        else             { CP_WAIT(0); }
        __syncthreads();

        const char* buf = smem + (c & 1) * BUF_SZ;
        const char* As = buf;
        const char* Bs = buf + A_T;

        #pragma unroll
        for (int ks = 0; ks < 4; ++ks) {
            const int koff = ks * 32 + tg * 8;

            uint32_t a[2][4];
            #pragma unroll
            for (int mt = 0; mt < 2; ++mt) {
                int r0 = warpM * 32 + mt * 16 + g;
                uint2 lo = *(const uint2*)(As + r0 * ROWB + koff);
                uint2 hi = *(const uint2*)(As + (r0 + 8) * ROWB + koff);
                a[mt][0] = lo.x;
                a[mt][1] = hi.x;
                a[mt][2] = lo.y;
                a[mt][3] = hi.y;
            }
            uint32_t b[4][2];
            #pragma unroll
            for (int nt = 0; nt < 4; ++nt) {
                int r = warpN * 32 + nt * 8 + g;
                uint2 bb = *(const uint2*)(Bs + r * ROWB + koff);
                b[nt][0] = bb.x;
                b[nt][1] = bb.y;
            }
            #pragma unroll
            for (int mt = 0; mt < 2; ++mt)
                #pragma unroll
                for (int nt = 0; nt < 4; ++nt)
                    mma_f16(acc[mt][nt], a[mt], b[nt]);
        }
        __syncthreads();
    }

    // ---- epilogue: bias + relu, float2 stores ----
    float2 bv[4];
    #pragma unroll
    for (int nt = 0; nt < 4; ++nt) {
        int col = colBase + warpN * 32 + nt * 8 + tg * 2;
        bv[nt].x = __ldg(bias + col);
        bv[nt].y = __ldg(bias + col + 1);
    }
    #pragma unroll
    for (int mt = 0; mt < 2; ++mt) {
        #pragma unroll
        for (int half = 0; half < 2; ++half) {
            int row = rowBase + warpM * 32 + mt * 16 + g + half * 8;
            if (row >= N_DST0) continue;
            #pragma unroll
            for (int nt = 0; nt < 4; ++nt) {
                int col = colBase + warpN * 32 + nt * 8 + tg * 2;
                float2 o;
                o.x = fmaxf(acc[mt][nt][half * 2 + 0] + bv[nt].x, 0.f);
                o.y = fmaxf(acc[mt][nt][half * 2 + 1] + bv[nt].y, 0.f);
                *(float2*)(g_h + (size_t)row * HID + col) = o;
            }
        }
    }
}

// ---------------- fused layer-1 aggregation + output layer -------------------
__global__ __launch_bounds__(256)
void k_agg1_out(const float* __restrict__ Ws1,
                const float* __restrict__ Wn1,
                const float* __restrict__ b1,
                float* __restrict__ out) {
    __shared__ float hd[HID];
    __shared__ float ha[HID];
    const int dst = blockIdx.x;
    const int t   = threadIdx.x;

    const int beg = g_off1[dst];
    const int end = g_off1[dst + 1];
    float acc = 0.f;
    for (int e = beg; e < end; ++e)
        acc += g_h[(size_t)g_src1[e] * HID + t];
    const float inv = (end > beg) ? 1.0f / (float)(end - beg) : 0.0f;
    ha[t] = acc * inv;
    hd[t] = g_h[(size_t)dst * HID + t];     // h_dst1 = h[:1000]
    __syncthreads();

    if (t < NCLS) {
        float s = b1[t];
        #pragma unroll 4
        for (int k = 0; k < HID; ++k)
            s += hd[k] * Ws1[k * NCLS + t] + ha[k] * Wn1[k * NCLS + t];
        out[dst * NCLS + t] = s;
    }
}

// ---------------- launch (single stream, graph-capture safe) -----------------
extern "C" void kernel_launch(void* const* d_in, const int* in_sizes, int n_in,
                              void* d_out, int out_size) {
    const float* x      = (const float*)d_in[0];
    const float* Wself0 = (const float*)d_in[1];
    const float* Wneigh0= (const float*)d_in[2];
    const float* b0     = (const float*)d_in[3];
    const float* Wself1 = (const float*)d_in[4];
    const float* Wneigh1= (const float*)d_in[5];
    const float* b1     = (const float*)d_in[6];
    const int*   e0_src = (const int*)d_in[7];
    const int*   e0_dst = (const int*)d_in[8];
    const int*   e1_src = (const int*)d_in[9];
    const int*   e1_dst = (const int*)d_in[10];
    float* out = (float*)d_out;

    static bool attr_set = false;
    if (!attr_set) {
        cudaFuncSetAttribute(k_gemm_mma, cudaFuncAttributeMaxDynamicSharedMemorySize, GEMM_SMEM);
        attr_set = true;
    }

    k_count     <<<(N_E0 + 255) / 256, 256>>>(e0_dst, e1_dst);
    k_scan      <<<2, 1024>>>();
    k_scatter   <<<(N_E0 + 255) / 256, 256>>>(e0_src, e0_dst, e1_src, e1_dst);
    k_agg0_prep <<<MEGA_BLKS, 128>>>(x, Wself0, Wneigh0);
    k_gemm_mma  <<<dim3((N_DST0 + 127) / 128, 4), 256, GEMM_SMEM>>>(b0);
    k_agg1_out  <<<N_DST1, 256>>>(Wself1, Wneigh1, b1, out);
}